// round 2
// baseline (speedup 1.0000x reference)
#include <cuda_runtime.h>
#include <cstdint>
#include <cstddef>

#define B_    128
#define T_    1024
#define HID_  512
#define VOC_  128
#define EMB_  16
#define NGRP  16      // independent batch groups
#define GSZ   8       // CTAs per group
#define RPG   8       // batch rows per group
#define JPC   64      // hidden columns per CTA

#define WS_PITCH 65   // padded pitch for W slice in smem (conflict-free both ways)
#define SMEM_SCAN ((HID_*WS_PITCH + VOC_*JPC + HID_*RPG)*4)

// ---- device scratch (no allocations allowed) ----
__device__ float g_P[VOC_*HID_];                    // P[v][j] = emb@W_ih^T + b_ih + b_hh
__device__ float g_hg[2][NGRP][HID_][RPG];          // double-buffered h, [buf][g][j][r]
__device__ float g_hs[(size_t)B_*T_*HID_];          // all hidden states for logits GEMM (256MB)
__device__ int   g_ctr[NGRP];                       // group barrier counters (monotonic, reset each run)

// ---------------------------------------------------------------------------
// Kernel 0: P[v][j] = sum_e emb[v][e]*W_ih[j][e] + b_ih[j] + b_hh[j]; reset ctrs
// ---------------------------------------------------------------------------
__global__ void prep_kernel(const float* __restrict__ emb, const float* __restrict__ W_ih,
                            const float* __restrict__ b_ih, const float* __restrict__ b_hh)
{
    int i = blockIdx.x*256 + threadIdx.x;    // exactly 65536 threads
    if (i < NGRP) g_ctr[i] = 0;
    int v = i >> 9;
    int j = i & 511;
    float s = b_ih[j] + b_hh[j];
    #pragma unroll
    for (int e = 0; e < EMB_; e++)
        s = fmaf(emb[v*EMB_ + e], W_ih[j*EMB_ + e], s);
    g_P[i] = s;
}

// ---------------------------------------------------------------------------
// Kernel 1: persistent scan. 16 groups x 8 CTAs; W_hh slice resident in smem.
// One group barrier per timestep (monotonic atomic counter + spin; all 128
// CTAs are co-resident: 1 CTA/SM by smem, grid=128 <= 148 SMs).
// ---------------------------------------------------------------------------
__global__ void __launch_bounds__(256, 1)
scan_kernel(const int* __restrict__ x, const float* __restrict__ W_hh)
{
    extern __shared__ float sm[];
    float* Ws = sm;                         // [512][65]  W_hh slice, k-major
    float* Ps = Ws + HID_*WS_PITCH;         // [128][64]  P slice
    float* hs = Ps + VOC_*JPC;              // [512][8]   current h (k-major, rows inner)
    __shared__ int toks[RPG];

    const int cta = blockIdx.x;
    const int g   = cta >> 3;               // group id
    const int c   = cta & 7;                // CTA within group
    const int j0  = c * JPC;                // owned hidden-col base
    const int tid = threadIdx.x;
    const int jl  = tid & 63;               // local col
    const int rp  = tid >> 6;               // row-pair id 0..3
    const int r0  = rp * 2;

    // Load W slice (transposed, padded): global coalesced, STS conflict-free.
    for (int i = tid; i < JPC*HID_; i += 256) {
        int jj = i >> 9, k = i & 511;
        Ws[k*WS_PITCH + jj] = W_hh[(j0 + jj)*HID_ + k];
    }
    // Load P slice
    for (int i = tid; i < VOC_*JPC; i += 256) {
        int v = i >> 6, jj = i & 63;
        Ps[i] = g_P[v*HID_ + j0 + jj];
    }
    // Zero own slice of h buffer 0 (h0 = 0)
    for (int i = tid; i < JPC*RPG; i += 256) {
        int jj = i >> 3, r = i & 7;
        g_hg[0][g][j0 + jj][r] = 0.f;
    }
    __threadfence();
    __syncthreads();

    int target = GSZ;
    if (tid == 0) {
        atomicAdd(&g_ctr[g], 1);
        while (*(volatile int*)&g_ctr[g] < target) { }
    }
    __syncthreads();
    target += GSZ;

    const float4* hgsrc0 = (const float4*)&g_hg[0][g][0][0];
    const float4* hgsrc1 = (const float4*)&g_hg[1][g][0][0];

    for (int t = 0; t < T_; t++) {
        // Stage full group h (16KB) from L2 into smem. .cv bypasses (stale) L1.
        const float4* src = (t & 1) ? hgsrc1 : hgsrc0;
        float4* dst4 = (float4*)hs;
        #pragma unroll
        for (int i = 0; i < 4; i++)
            dst4[tid + i*256] = __ldcv(src + tid + i*256);
        if (tid < RPG) toks[tid] = x[(g*RPG + tid)*T_ + t];
        __syncthreads();

        // acc init = precomputed input projection (token lookup)
        float a0 = Ps[toks[r0    ]*JPC + jl];
        float a1 = Ps[toks[r0 + 1]*JPC + jl];

        // h_new[r][j] = tanh(P + sum_k h[r][k] * W_hh[j][k])
        #pragma unroll 8
        for (int k = 0; k < HID_; k++) {
            float  w  = Ws[k*WS_PITCH + jl];                     // conflict-free
            float2 h2 = *(const float2*)(hs + k*RPG + r0);       // warp broadcast
            a0 = fmaf(w, h2.x, a0);
            a1 = fmaf(w, h2.y, a1);
        }
        a0 = tanhf(a0);
        a1 = tanhf(a1);

        // Publish: next-step h buffer + hs archive for logits GEMM
        int j = j0 + jl;
        *(float2*)&g_hg[(t & 1) ^ 1][g][j][r0] = make_float2(a0, a1);
        int b0 = g*RPG + r0;
        g_hs[(size_t)(b0*T_ + t)*HID_ + j]       = a0;
        g_hs[(size_t)((b0 + 1)*T_ + t)*HID_ + j] = a1;

        __threadfence();
        __syncthreads();
        if (tid == 0) {
            atomicAdd(&g_ctr[g], 1);
            while (*(volatile int*)&g_ctr[g] < target) { }
        }
        __syncthreads();
        target += GSZ;
    }
}

// ---------------------------------------------------------------------------
// Kernel 2: logits = hs[M=131072,512] @ W_fc^T[512,128] + b_fc
// CTA: 64 rows x 128 vocab; thread micro-tile 4x8 (v interleaved stride 16
// so scalar w-loads are bank-conflict-free).
// ---------------------------------------------------------------------------
__global__ void __launch_bounds__(256)
logits_kernel(const float* __restrict__ W_fc, const float* __restrict__ b_fc,
              float* __restrict__ out)
{
    __shared__ float As [64*33];
    __shared__ float Wsh[128*33];
    const int mb  = blockIdx.x * 64;
    const int tid = threadIdx.x;
    const int tv  = tid & 15;         // v lane: handles v = tv + 16*vi
    const int tm  = tid >> 4;         // m group: handles m = tm*4 + mi

    float acc[4][8];
    #pragma unroll
    for (int vi = 0; vi < 8; vi++) {
        float bv = b_fc[tv + 16*vi];
        #pragma unroll
        for (int mi = 0; mi < 4; mi++) acc[mi][vi] = bv;
    }

    for (int k0 = 0; k0 < HID_; k0 += 32) {
        #pragma unroll
        for (int i = 0; i < 8; i++) {            // 64x32 A chunk
            int idx = tid + i*256;
            int m = idx >> 5, k = idx & 31;
            As[m*33 + k] = g_hs[(size_t)(mb + m)*HID_ + k0 + k];
        }
        #pragma unroll
        for (int i = 0; i < 16; i++) {           // 128x32 W chunk
            int idx = tid + i*256;
            int v = idx >> 5, k = idx & 31;
            Wsh[v*33 + k] = W_fc[v*HID_ + k0 + k];
        }
        __syncthreads();
        #pragma unroll 8
        for (int k = 0; k < 32; k++) {
            float a[4], w[8];
            #pragma unroll
            for (int mi = 0; mi < 4; mi++) a[mi] = As[(tm*4 + mi)*33 + k];
            #pragma unroll
            for (int vi = 0; vi < 8; vi++) w[vi] = Wsh[(tv + 16*vi)*33 + k];
            #pragma unroll
            for (int mi = 0; mi < 4; mi++)
                #pragma unroll
                for (int vi = 0; vi < 8; vi++)
                    acc[mi][vi] = fmaf(a[mi], w[vi], acc[mi][vi]);
        }
        __syncthreads();
    }
    #pragma unroll
    for (int mi = 0; mi < 4; mi++) {
        size_t row = (size_t)(mb + tm*4 + mi) * VOC_;
        #pragma unroll
        for (int vi = 0; vi < 8; vi++)
            out[row + tv + 16*vi] = acc[mi][vi];
    }
}

// ---------------------------------------------------------------------------
extern "C" void kernel_launch(void* const* d_in, const int* in_sizes, int n_in,
                              void* d_out, int out_size)
{
    const int*   x    = (const int*)  d_in[0];
    const float* emb  = (const float*)d_in[1];
    const float* W_ih = (const float*)d_in[2];
    const float* W_hh = (const float*)d_in[3];
    const float* b_ih = (const float*)d_in[4];
    const float* b_hh = (const float*)d_in[5];
    const float* W_fc = (const float*)d_in[6];
    const float* b_fc = (const float*)d_in[7];
    float* out = (float*)d_out;

    cudaFuncSetAttribute(scan_kernel, cudaFuncAttributeMaxDynamicSharedMemorySize, SMEM_SCAN);

    prep_kernel  <<<256, 256>>>(emb, W_ih, b_ih, b_hh);
    scan_kernel  <<<NGRP*GSZ, 256, SMEM_SCAN>>>(x, W_hh);
    logits_kernel<<<(B_*T_)/64, 256>>>(W_fc, b_fc, out);
}